// round 6
// baseline (speedup 1.0000x reference)
#include <cuda_runtime.h>
#include <math.h>
#include <float.h>

// Problem constants
#define B_    2
#define S_    2048
#define BS_   4096
#define V_    50257
#define V4_   50260          // V_ padded to multiple of 4 (row stride for tables)
#define N_    512
#define NM1_  511
#define NZ2_  16
#define CH2_  (BS_/NZ2_)     // 256 samples per z-slice
#define TPB_T 8              // tokens per block in k_tables_direct

#define SCORE_OFF  ((size_t)BS_ * (size_t)V_)
#define MEANDT_OFF (SCORE_OFF + (size_t)BS_ * (size_t)S_)

// dynamic smem layout for k_tables_direct (floats)
#define DS_ROW   0            // 8 x 512
#define DS_A     4096         // 512 x 8  (stage A by rank)
#define DS_D     8192         // 512 x 8
#define DS_SW    12288        // 512
#define DS_SB    12800
#define DS_SS    13312
#define DS_PERM  13824        // int 512
#define DS_RANK  14336        // int 512
#define DS_TOT   14848        // floats -> 59392 bytes

// ----------------------------- device scratch -----------------------------
__device__ float g_rv[BS_];
__device__ float g_k1[BS_];
__device__ float g_tgt[BS_];
__device__ float g_r[BS_];
__device__ float g_c[BS_];
__device__ int   g_list[BS_];
__device__ int   g_krank[BS_];
__device__ int   g_U;

__device__ float g_thresh[N_];   // sorted keys, normal order (for binary search)
// metadata in swizzled layout: slot(j) = (j%16)*32 + j/16  (j = sorted position)
__device__ float g_sw[N_];
__device__ float g_sb[N_];
__device__ float g_ss[N_];
__device__ int   g_perm[N_];     // original w_out column (perm(j)+1), 0 for dummy
__device__ int   g_rank[N_];     // compacted rank or -1, swizzled layout

__device__ __align__(16) float g_A [(size_t)N_ * V4_];   // suffix tables at used ranks
__device__ __align__(16) float g_D [(size_t)N_ * V4_];   // D' = suffB - suffC
__device__ __align__(16) float g_E [V4_];                // totalC + b_out
__device__ __align__(16) float g_W0[V4_];                // w_out[:,0]

// ----------------------------- helpers -----------------------------
__device__ __forceinline__ float blockReduceSum(float v, float* sh) {
    #pragma unroll
    for (int o = 16; o > 0; o >>= 1) v += __shfl_down_sync(0xffffffffu, v, o);
    int lane = threadIdx.x & 31;
    int w    = threadIdx.x >> 5;
    if (lane == 0) sh[w] = v;
    __syncthreads();
    if (w == 0) {
        v = (lane < (int)(blockDim.x >> 5)) ? sh[lane] : 0.f;
        #pragma unroll
        for (int o = 16; o > 0; o >>= 1) v += __shfl_down_sync(0xffffffffu, v, o);
        if (lane == 0) sh[0] = v;
    }
    __syncthreads();
    float r = sh[0];
    __syncthreads();
    return r;
}

__device__ __forceinline__ float clipf(float x, float lo, float hi) {
    return fminf(fmaxf(x, lo), hi);
}

// ----------------------------- K0: fused embed + sort -----------------------------
// Block 0: bitonic sort of clip thresholds. Blocks 1..8: embedding (512 each).
// Sentinels: real breakpoints in (0,1); "never clips" = 2.0; dummy slot 511 = 3.0
// (unique max -> pinned at sorted position 511 under strict comparisons).
__global__ void __launch_bounds__(512) k_init(const int* __restrict__ x,
                                              const float* __restrict__ dt,
                                              const float* __restrict__ r0,
                                              const float* __restrict__ w_diff,
                                              const float* __restrict__ b_diff,
                                              float* __restrict__ out, size_t out_size) {
    int tid = threadIdx.x;
    if (blockIdx.x != 0) {
        int gid = (blockIdx.x - 1) * 512 + tid;
        float r = r0[x[gid]];
        g_rv[gid] = r / fmaxf(fabsf(r), 1e-12f);
        if (gid == 0 && out_size > MEANDT_OFF) {
            float d0 = clipf(dt[0], 0.f, 1.f);
            float d1 = clipf(dt[1], 0.f, 1.f);
            out[MEANDT_OFF] = 0.5f * (d0 + d1);
        }
        return;
    }

    __shared__ float skey[N_];
    __shared__ int   sval[N_];

    float t = 3.0f;
    if (tid < NM1_) {
        float w = w_diff[tid], bb = b_diff[tid];
        t = 2.0f;
        if (w > 0.f && (w + bb) > 1.f)        t = (1.f - bb) / w;
        else if (w < 0.f && (w + bb) < -1.f)  t = (-1.f - bb) / w;
    }
    skey[tid] = t;
    sval[tid] = tid;
    __syncthreads();

    for (int ksz = 2; ksz <= N_; ksz <<= 1) {
        for (int jsz = ksz >> 1; jsz > 0; jsz >>= 1) {
            int ixj = tid ^ jsz;
            if (ixj > tid) {
                bool up = ((tid & ksz) == 0);
                float a = skey[tid], c = skey[ixj];
                bool sw = up ? (a > c) : (a < c);
                if (sw) {
                    skey[tid] = c; skey[ixj] = a;
                    int tmp = sval[tid]; sval[tid] = sval[ixj]; sval[ixj] = tmp;
                }
            }
            __syncthreads();
        }
    }

    int n = sval[tid];
    float key = skey[tid];
    g_thresh[tid] = key;
    int slot = ((tid & 15) << 5) | (tid >> 4);
    if (n < NM1_) {
        float w = w_diff[n], bb = b_diff[n];
        g_sw[slot]   = w;
        g_sb[slot]   = bb;
        g_ss[slot]   = (key >= 2.0f) ? 0.f : (w > 0.f ? 1.f : -1.f);
        g_perm[slot] = n + 1;
    } else {
        g_sw[slot] = 0.f; g_sb[slot] = 0.f; g_ss[slot] = 0.f;
        g_perm[slot] = 0;
    }
}

// ----------------------------- K1: score1 stats + k1 -----------------------------
__global__ void k_step1(const float* __restrict__ dt) {
    __shared__ float srow[S_];
    __shared__ float sred[32];
    int gid = blockIdx.x;
    int b = gid >> 11;
    int i = gid & (S_ - 1);

    for (int j = threadIdx.x; j < S_; j += blockDim.x) srow[j] = g_rv[b * S_ + j];
    __syncthreads();
    float ri = srow[i];

    float s1 = 0.f, s2 = 0.f;
    for (int j = threadIdx.x; j < S_; j += blockDim.x) {
        float d = fabsf(ri - srow[j]);
        s1 += d;
        s2 += d * d;
    }
    s1 = blockReduceSum(s1, sred);
    s2 = blockReduceSum(s2, sred);

    float mean = s1 * (1.f / (float)S_);
    float ssq  = fmaxf(s2 - s1 * mean, 0.f);
    float var  = ssq * (1.f / (float)(S_ - 1));
    float thr  = fmaxf(mean + 2.f * sqrtf(var), 1e-12f);
    float inv  = 1.f / thr;

    float acc = 0.f;
    for (int j = threadIdx.x; j < i; j += blockDim.x) {
        float d = fabsf(ri - srow[j]);
        if (d <= thr) acc += (1.f - d * inv) * srow[j];
    }
    acc = blockReduceSum(acc, sred);

    if (threadIdx.x == 0) {
        float dtc = clipf(dt[b], 0.f, 1.f);
        float k1  = clipf(dtc * acc, -1.f, 1.f);
        g_k1[gid]  = k1;
        g_tgt[gid] = ri + k1;
    }
}

// ----------------------------- K2: score2 + outputs -----------------------------
__global__ void k_step2(const float* __restrict__ dt, float* __restrict__ out,
                        int write_score) {
    __shared__ float srow[S_];
    __shared__ float sred[32];
    int gid = blockIdx.x;
    int b = gid >> 11;
    int i = gid & (S_ - 1);

    for (int j = threadIdx.x; j < S_; j += blockDim.x) srow[j] = g_tgt[b * S_ + j];
    __syncthreads();
    float ti = srow[i];

    float s1 = 0.f, s2 = 0.f;
    for (int j = threadIdx.x; j < S_; j += blockDim.x) {
        float d = fabsf(ti - srow[j]);
        s1 += d;
        s2 += d * d;
    }
    s1 = blockReduceSum(s1, sred);
    s2 = blockReduceSum(s2, sred);

    float mean = s1 * (1.f / (float)S_);
    float ssq  = fmaxf(s2 - s1 * mean, 0.f);
    float var  = ssq * (1.f / (float)(S_ - 1));
    float thr  = fmaxf(mean + 2.f * sqrtf(var), 1e-12f);
    float inv  = 1.f / thr;

    float acc = 0.f, accs = 0.f;
    size_t rowoff = SCORE_OFF + (size_t)gid * S_;
    for (int j = threadIdx.x; j < S_; j += blockDim.x) {
        float d  = fabsf(ti - srow[j]);
        float sc = (j < i && d <= thr) ? (1.f - d * inv) : 0.f;
        if (write_score) out[rowoff + j] = sc;
        acc  += sc * srow[j];
        accs += sc;
    }
    acc  = blockReduceSum(acc, sred);
    accs = blockReduceSum(accs, sred);

    if (threadIdx.x == 0) {
        float dtc = clipf(dt[b], 0.f, 1.f);
        float k2  = clipf(dtc * acc, -1.f, 1.f);
        float z   = g_rv[gid] + 0.5f * (g_k1[gid] + k2);
        g_r[gid]  = z / fmaxf(fabsf(z), 1e-12f);
        g_c[gid]  = clipf(accs * (1.f / (float)S_), 0.f, 1.f);
    }
}

// ----------------------------- K3: bucket (kidx + parallel scan + rank + scatter) --------------
__global__ void __launch_bounds__(512) k_bucket() {
    __shared__ float thr[N_];
    __shared__ int   s1[N_];     // counts -> inclusive scan
    __shared__ int   s2a[N_];    // used flags -> inclusive scan
    __shared__ int   posA[N_];
    __shared__ int   rnkS[N_];
    int tid = threadIdx.x;

    thr[tid] = g_thresh[tid];
    s1[tid] = 0;
    __syncthreads();

    int kx[BS_ / 512];
    #pragma unroll
    for (int q = 0; q < BS_ / 512; q++) {
        int sid = q * 512 + tid;
        float c = g_c[sid];
        int lo = 0, hi = N_;
        while (lo < hi) {
            int mid = (lo + hi) >> 1;
            if (thr[mid] <= c) lo = mid + 1; else hi = mid;
        }
        kx[q] = lo;                  // provably <= 511 (sentinel keys 2.0/3.0 > 1 >= c)
        atomicAdd(&s1[lo], 1);
    }
    __syncthreads();

    int myc = s1[tid];
    int myf = (myc > 0) ? 1 : 0;
    s2a[tid] = myf;
    __syncthreads();

    // inclusive Hillis-Steele scan of counts and flags
    for (int off = 1; off < N_; off <<= 1) {
        int a = 0, b = 0;
        if (tid >= off) { a = s1[tid - off]; b = s2a[tid - off]; }
        __syncthreads();
        s1[tid] += a; s2a[tid] += b;
        __syncthreads();
    }

    posA[tid] = s1[tid] - myc;                 // exclusive prefix of counts
    int r = myf ? (s2a[tid] - 1) : -1;         // rank among used slots
    rnkS[tid] = r;
    g_rank[((tid & 15) << 5) | (tid >> 4)] = r;  // swizzled for k_tables_direct
    if (tid == N_ - 1) g_U = s2a[N_ - 1];
    __syncthreads();

    #pragma unroll
    for (int q = 0; q < BS_ / 512; q++) {
        int sid = q * 512 + tid;
        int p = atomicAdd(&posA[kx[q]], 1);
        g_list[p] = sid;
        g_krank[sid] = rnkS[kx[q]];
    }
}

// ----------------------------- K4: tables directly from w_out rows -----------------------------
// One warp per token t (8 tokens/block). Lane l owns sorted positions j = l*16+i;
// metadata slot for j is i*32 + l (conflict-free SMEM). Results staged in SMEM
// by rank, then written coalesced (8 consecutive tokens per rank row = full 32B sectors).
__global__ void __launch_bounds__(256) k_tables_direct(const float* __restrict__ w_out,
                                                       const float* __restrict__ b_out) {
    extern __shared__ float dyn[];
    float* srowb = dyn + DS_ROW;
    float* stA   = dyn + DS_A;
    float* stD   = dyn + DS_D;
    float* ssw   = dyn + DS_SW;
    float* ssb   = dyn + DS_SB;
    float* sss   = dyn + DS_SS;
    int*   sperm = (int*)(dyn + DS_PERM);
    int*   srank = (int*)(dyn + DS_RANK);

    int tid = threadIdx.x;
    for (int j = tid; j < N_; j += 256) {
        ssw[j] = g_sw[j]; ssb[j] = g_sb[j]; sss[j] = g_ss[j];
        sperm[j] = g_perm[j]; srank[j] = g_rank[j];
    }

    int wid  = tid >> 5;
    int lane = tid & 31;
    int t = blockIdx.x * TPB_T + wid;
    bool tv = (t < V_);

    if (tv) {
        const float4* rp = (const float4*)(w_out + (size_t)t * N_);
        float4* sp = (float4*)(srowb + wid * N_);
        #pragma unroll
        for (int q = 0; q < 4; q++) sp[q * 32 + lane] = rp[q * 32 + lane];
    }
    __syncthreads();

    if (tv) {
        const float* row = srowb + wid * N_;

        // pass 1: per-lane suffix totals over its 16 positions
        float ta = 0.f, tb = 0.f, tc = 0.f;
        #pragma unroll
        for (int i = 15; i >= 0; i--) {
            int m = i * 32 + lane;
            float w = row[sperm[m]];
            ta = fmaf(w, ssw[m], ta);
            tb = fmaf(w, ssb[m], tb);
            tc = fmaf(w, sss[m], tc);
        }

        // inclusive suffix scan across lanes
        float ia = ta, ib = tb, ic = tc;
        #pragma unroll
        for (int off = 1; off < 32; off <<= 1) {
            float xa = __shfl_down_sync(0xffffffffu, ia, off);
            float xb = __shfl_down_sync(0xffffffffu, ib, off);
            float xc = __shfl_down_sync(0xffffffffu, ic, off);
            if (lane + off < 32) { ia += xa; ib += xb; ic += xc; }
        }
        float ba = ia - ta, bb = ib - tb, bc = ic - tc;
        float totc = __shfl_sync(0xffffffffu, ic, 0);

        // pass 2: walk down, stage at used ranks
        float aa = ba, ab = bb, ac = bc;
        #pragma unroll
        for (int i = 15; i >= 0; i--) {
            int m = i * 32 + lane;
            float w = row[sperm[m]];
            aa = fmaf(w, ssw[m], aa);
            ab = fmaf(w, ssb[m], ab);
            ac = fmaf(w, sss[m], ac);
            int rk = srank[m];
            if (rk >= 0) {
                stA[rk * TPB_T + wid] = aa;
                stD[rk * TPB_T + wid] = ab - ac;
            }
        }

        if (lane == 0) {
            g_W0[t] = row[0];
            g_E[t]  = totc + b_out[t];
        }
    }
    __syncthreads();

    // coalesced write-out: 8 lanes cover 8 consecutive tokens of one rank row
    int U = g_U;
    int t0 = blockIdx.x * TPB_T;
    int rloc = tid >> 3;           // 0..31
    int tl   = tid & 7;
    int tt   = t0 + tl;
    if (tt < V_) {
        for (int base = 0; base < U; base += 32) {
            int rk = base + rloc;
            if (rk < U) {
                g_A[(size_t)rk * V4_ + tt] = stA[rk * TPB_T + tl];
                g_D[(size_t)rk * V4_ + tt] = stD[rk * TPB_T + tl];
            }
        }
    }
}

// ----------------------------- K5: logits -----------------------------
__global__ void __launch_bounds__(256) k_logits(float* __restrict__ out) {
    __shared__ int   slist[CH2_];
    __shared__ int   srk[CH2_];
    __shared__ float sr[CH2_];
    __shared__ float sc[CH2_];

    {
        int p = threadIdx.x;
        int sid = g_list[blockIdx.y * CH2_ + p];
        slist[p] = sid;
        srk[p]   = g_krank[sid];
        sr[p]    = g_r[sid];
        sc[p]    = g_c[sid];
    }
    __syncthreads();

    int t0 = blockIdx.x * 1024 + threadIdx.x * 4;
    if (t0 >= V4_) return;

    const float4 w0 = *(const float4*)(g_W0 + t0);
    const float4 E  = *(const float4*)(g_E + t0);
    bool v0 = (t0     < V_);
    bool v1 = (t0 + 1 < V_);
    bool v2 = (t0 + 2 < V_);
    bool v3 = (t0 + 3 < V_);

    int kcur = -1;
    float4 A = make_float4(0.f, 0.f, 0.f, 0.f);
    float4 D = make_float4(0.f, 0.f, 0.f, 0.f);

    #pragma unroll 4
    for (int p = 0; p < CH2_; p++) {
        int rk = srk[p];
        if (rk != kcur) {
            A = *(const float4*)(g_A + (size_t)rk * V4_ + t0);
            float4 Dp = *(const float4*)(g_D + (size_t)rk * V4_ + t0);
            D = make_float4(Dp.x + E.x, Dp.y + E.y, Dp.z + E.z, Dp.w + E.w);
            kcur = rk;
        }
        float r = sr[p], c = sc[p];
        float x0 = fmaf(r, w0.x, fmaf(c, A.x, D.x));
        float x1 = fmaf(r, w0.y, fmaf(c, A.y, D.y));
        float x2 = fmaf(r, w0.z, fmaf(c, A.z, D.z));
        float x3 = fmaf(r, w0.w, fmaf(c, A.w, D.w));
        x0 = fminf(fmaxf(x0, -2.f), 2.f);
        x1 = fminf(fmaxf(x1, -2.f), 2.f);
        x2 = fminf(fmaxf(x2, -2.f), 2.f);
        x3 = fminf(fmaxf(x3, -2.f), 2.f);
        size_t o = (size_t)slist[p] * V_ + t0;
        if (v0) out[o]     = x0;
        if (v1) out[o + 1] = x1;
        if (v2) out[o + 2] = x2;
        if (v3) out[o + 3] = x3;
    }
}

// ----------------------------- launch -----------------------------
extern "C" void kernel_launch(void* const* d_in, const int* in_sizes, int n_in,
                              void* d_out, int out_size) {
    const int*   x      = (const int*)  d_in[0];
    const float* dt     = (const float*)d_in[1];
    const float* r0     = (const float*)d_in[2];
    const float* w_diff = (const float*)d_in[3];
    const float* b_diff = (const float*)d_in[4];
    const float* w_out  = (const float*)d_in[5];
    const float* b_out  = (const float*)d_in[6];
    float* out = (float*)d_out;
    size_t osz = (size_t)out_size;

    int write_score = (osz >= SCORE_OFF + (size_t)BS_ * S_) ? 1 : 0;

    static bool s_attr = false;
    if (!s_attr) {
        cudaFuncSetAttribute(k_tables_direct,
                             cudaFuncAttributeMaxDynamicSharedMemorySize,
                             DS_TOT * (int)sizeof(float));
        s_attr = true;
    }

    k_init<<<1 + BS_ / 512, 512>>>(x, dt, r0, w_diff, b_diff, out, osz);
    k_step1<<<BS_, 256>>>(dt);
    k_step2<<<BS_, 256>>>(dt, out, write_score);
    k_bucket<<<1, 512>>>();

    k_tables_direct<<<(V_ + TPB_T - 1) / TPB_T, 256, DS_TOT * sizeof(float)>>>(w_out, b_out);

    dim3 lg((V4_ + 1023) / 1024, NZ2_);
    k_logits<<<lg, 256>>>(out);
}

// round 7
// speedup vs baseline: 1.0284x; 1.0284x over previous
#include <cuda_runtime.h>
#include <math.h>
#include <float.h>

// Problem constants
#define B_    2
#define S_    2048
#define BS_   4096
#define V_    50257
#define V4_   50260          // V_ padded to multiple of 4 (row stride for tables)
#define N_    512
#define NM1_  511
#define NZ2_  16
#define CH2_  (BS_/NZ2_)     // 256 samples per z-slice
#define WPB_T 8              // warps (tokens) per block in k_tables_direct

#define SCORE_OFF  ((size_t)BS_ * (size_t)V_)
#define MEANDT_OFF (SCORE_OFF + (size_t)BS_ * (size_t)S_)

// ----------------------------- device scratch -----------------------------
__device__ float g_rv[BS_];
__device__ float g_k1[BS_];
__device__ float g_tgt[BS_];
__device__ float g_r[BS_];
__device__ float g_c[BS_];
__device__ int   g_list[BS_];
__device__ int   g_krank[BS_];
__device__ int   g_done;

__device__ float g_thresh[N_];   // sorted keys, normal order (for binary search)
// metadata in swizzled layout: slot(j) = (j%16)*32 + j/16  (j = sorted position)
__device__ float g_sw[N_];
__device__ float g_sb[N_];
__device__ float g_ss[N_];
__device__ int   g_perm[N_];     // original w_out column (perm(j)+1), 0 for dummy
__device__ int   g_rank[N_];     // compacted rank or -1, swizzled layout

__device__ __align__(16) float g_A [(size_t)N_ * V4_];   // suffix tables at used ranks
__device__ __align__(16) float g_D [(size_t)N_ * V4_];   // D' = suffB - suffC
__device__ __align__(16) float g_E [V4_];                // totalC + b_out
__device__ __align__(16) float g_W0[V4_];                // w_out[:,0]

// ----------------------------- helpers -----------------------------
__device__ __forceinline__ float blockReduceSum(float v, float* sh) {
    #pragma unroll
    for (int o = 16; o > 0; o >>= 1) v += __shfl_down_sync(0xffffffffu, v, o);
    int lane = threadIdx.x & 31;
    int w    = threadIdx.x >> 5;
    if (lane == 0) sh[w] = v;
    __syncthreads();
    if (w == 0) {
        v = (lane < (int)(blockDim.x >> 5)) ? sh[lane] : 0.f;
        #pragma unroll
        for (int o = 16; o > 0; o >>= 1) v += __shfl_down_sync(0xffffffffu, v, o);
        if (lane == 0) sh[0] = v;
    }
    __syncthreads();
    float r = sh[0];
    __syncthreads();
    return r;
}

__device__ __forceinline__ float clipf(float x, float lo, float hi) {
    return fminf(fmaxf(x, lo), hi);
}

// ----------------------------- K0: fused embed + sort (+ g_done reset) -----------------------------
// Block 0: bitonic sort of clip thresholds. Blocks 1..8: embedding (512 each).
// Sentinels: real breakpoints in (0,1); "never clips" = 2.0; dummy slot 511 = 3.0
// (unique max -> pinned at sorted position 511 under strict comparisons).
__global__ void __launch_bounds__(512) k_init(const int* __restrict__ x,
                                              const float* __restrict__ dt,
                                              const float* __restrict__ r0,
                                              const float* __restrict__ w_diff,
                                              const float* __restrict__ b_diff,
                                              float* __restrict__ out, size_t out_size) {
    int tid = threadIdx.x;
    if (blockIdx.x != 0) {
        int gid = (blockIdx.x - 1) * 512 + tid;
        float r = r0[x[gid]];
        g_rv[gid] = r / fmaxf(fabsf(r), 1e-12f);
        if (gid == 0 && out_size > MEANDT_OFF) {
            float d0 = clipf(dt[0], 0.f, 1.f);
            float d1 = clipf(dt[1], 0.f, 1.f);
            out[MEANDT_OFF] = 0.5f * (d0 + d1);
        }
        return;
    }

    if (tid == 0) g_done = 0;    // reset for step2's last-block detection

    __shared__ float skey[N_];
    __shared__ int   sval[N_];

    float t = 3.0f;
    if (tid < NM1_) {
        float w = w_diff[tid], bb = b_diff[tid];
        t = 2.0f;
        if (w > 0.f && (w + bb) > 1.f)        t = (1.f - bb) / w;
        else if (w < 0.f && (w + bb) < -1.f)  t = (-1.f - bb) / w;
    }
    skey[tid] = t;
    sval[tid] = tid;
    __syncthreads();

    for (int ksz = 2; ksz <= N_; ksz <<= 1) {
        for (int jsz = ksz >> 1; jsz > 0; jsz >>= 1) {
            int ixj = tid ^ jsz;
            if (ixj > tid) {
                bool up = ((tid & ksz) == 0);
                float a = skey[tid], c = skey[ixj];
                bool sw = up ? (a > c) : (a < c);
                if (sw) {
                    skey[tid] = c; skey[ixj] = a;
                    int tmp = sval[tid]; sval[tid] = sval[ixj]; sval[ixj] = tmp;
                }
            }
            __syncthreads();
        }
    }

    int n = sval[tid];
    float key = skey[tid];
    g_thresh[tid] = key;
    int slot = ((tid & 15) << 5) | (tid >> 4);
    if (n < NM1_) {
        float w = w_diff[n], bb = b_diff[n];
        g_sw[slot]   = w;
        g_sb[slot]   = bb;
        g_ss[slot]   = (key >= 2.0f) ? 0.f : (w > 0.f ? 1.f : -1.f);
        g_perm[slot] = n + 1;
    } else {
        g_sw[slot] = 0.f; g_sb[slot] = 0.f; g_ss[slot] = 0.f;
        g_perm[slot] = 0;
    }
}

// ----------------------------- K1: score1 stats + k1 -----------------------------
__global__ void k_step1(const float* __restrict__ dt) {
    __shared__ float srow[S_];
    __shared__ float sred[32];
    int gid = blockIdx.x;
    int b = gid >> 11;
    int i = gid & (S_ - 1);

    for (int j = threadIdx.x; j < S_; j += blockDim.x) srow[j] = g_rv[b * S_ + j];
    __syncthreads();
    float ri = srow[i];

    float s1 = 0.f, s2 = 0.f;
    for (int j = threadIdx.x; j < S_; j += blockDim.x) {
        float d = fabsf(ri - srow[j]);
        s1 += d;
        s2 += d * d;
    }
    s1 = blockReduceSum(s1, sred);
    s2 = blockReduceSum(s2, sred);

    float mean = s1 * (1.f / (float)S_);
    float ssq  = fmaxf(s2 - s1 * mean, 0.f);
    float var  = ssq * (1.f / (float)(S_ - 1));
    float thr  = fmaxf(mean + 2.f * sqrtf(var), 1e-12f);
    float inv  = 1.f / thr;

    float acc = 0.f;
    for (int j = threadIdx.x; j < i; j += blockDim.x) {
        float d = fabsf(ri - srow[j]);
        if (d <= thr) acc += (1.f - d * inv) * srow[j];
    }
    acc = blockReduceSum(acc, sred);

    if (threadIdx.x == 0) {
        float dtc = clipf(dt[b], 0.f, 1.f);
        float k1  = clipf(dtc * acc, -1.f, 1.f);
        g_k1[gid]  = k1;
        g_tgt[gid] = ri + k1;
    }
}

// ----------------------------- K2: score2 + outputs + fused bucket (last block) ------------------
__global__ void __launch_bounds__(512) k_step2(const float* __restrict__ dt,
                                               float* __restrict__ out, int write_score) {
    __shared__ float srow[S_];
    __shared__ float sred[32];
    __shared__ int   sdone;
    int gid = blockIdx.x;
    int b = gid >> 11;
    int i = gid & (S_ - 1);
    int tid = threadIdx.x;

    for (int j = tid; j < S_; j += 512) srow[j] = g_tgt[b * S_ + j];
    __syncthreads();
    float ti = srow[i];

    float s1 = 0.f, s2 = 0.f;
    #pragma unroll
    for (int q = 0; q < 4; q++) {
        float d = fabsf(ti - srow[q * 512 + tid]);
        s1 += d;
        s2 += d * d;
    }
    s1 = blockReduceSum(s1, sred);
    s2 = blockReduceSum(s2, sred);

    float mean = s1 * (1.f / (float)S_);
    float ssq  = fmaxf(s2 - s1 * mean, 0.f);
    float var  = ssq * (1.f / (float)(S_ - 1));
    float thr  = fmaxf(mean + 2.f * sqrtf(var), 1e-12f);
    float inv  = 1.f / thr;

    float acc = 0.f, accs = 0.f;
    size_t rowoff = SCORE_OFF + (size_t)gid * S_;
    #pragma unroll
    for (int q = 0; q < 4; q++) {
        int j = q * 512 + tid;
        float d  = fabsf(ti - srow[j]);
        float sc = (j < i && d <= thr) ? (1.f - d * inv) : 0.f;
        if (write_score) out[rowoff + j] = sc;
        acc  += sc * srow[j];
        accs += sc;
    }
    acc  = blockReduceSum(acc, sred);
    accs = blockReduceSum(accs, sred);

    if (tid == 0) {
        float dtc = clipf(dt[b], 0.f, 1.f);
        float k2  = clipf(dtc * acc, -1.f, 1.f);
        float z   = g_rv[gid] + 0.5f * (g_k1[gid] + k2);
        g_r[gid]  = z / fmaxf(fabsf(z), 1e-12f);
        g_c[gid]  = clipf(accs * (1.f / (float)S_), 0.f, 1.f);
    }

    // ---- last-block-done: the final block to finish runs the bucket stage ----
    __threadfence();
    if (tid == 0) {
        int old = atomicAdd(&g_done, 1);
        sdone = (old == (int)gridDim.x - 1) ? 1 : 0;
    }
    __syncthreads();
    if (!sdone) return;

    // bucket: kidx + parallel scan + rank + scatter (512 threads)
    __shared__ float bthr[N_];
    __shared__ int   bs1[N_];
    __shared__ int   bs2[N_];
    __shared__ int   posA[N_];
    __shared__ int   rnkS[N_];

    bthr[tid] = g_thresh[tid];
    bs1[tid] = 0;
    __syncthreads();

    int kx[BS_ / 512];
    #pragma unroll
    for (int q = 0; q < BS_ / 512; q++) {
        int sid = q * 512 + tid;
        float c = g_c[sid];
        int lo = 0, hi = N_;
        while (lo < hi) {
            int mid = (lo + hi) >> 1;
            if (bthr[mid] <= c) lo = mid + 1; else hi = mid;
        }
        kx[q] = lo;                  // provably <= 511 (sentinel keys 2.0/3.0 > 1 >= c)
        atomicAdd(&bs1[lo], 1);
    }
    __syncthreads();

    int myc = bs1[tid];
    int myf = (myc > 0) ? 1 : 0;
    bs2[tid] = myf;
    __syncthreads();

    for (int off = 1; off < N_; off <<= 1) {
        int a = 0, bb2 = 0;
        if (tid >= off) { a = bs1[tid - off]; bb2 = bs2[tid - off]; }
        __syncthreads();
        bs1[tid] += a; bs2[tid] += bb2;
        __syncthreads();
    }

    posA[tid] = bs1[tid] - myc;
    int r = myf ? (bs2[tid] - 1) : -1;
    rnkS[tid] = r;
    g_rank[((tid & 15) << 5) | (tid >> 4)] = r;
    __syncthreads();

    #pragma unroll
    for (int q = 0; q < BS_ / 512; q++) {
        int sid = q * 512 + tid;
        int p = atomicAdd(&posA[kx[q]], 1);
        g_list[p] = sid;
        g_krank[sid] = rnkS[kx[q]];
    }
}

// ----------------------------- K3: tables directly from w_out rows -----------------------------
// One warp per token t. Lane l owns sorted positions j = l*16 + i (i = 0..15);
// metadata slot for j is i*32 + l (conflict-free SMEM access).
__global__ void __launch_bounds__(256) k_tables_direct(const float* __restrict__ w_out,
                                                       const float* __restrict__ b_out) {
    __shared__ float ssw[N_], ssb[N_], sss[N_];
    __shared__ int   sperm[N_], srank[N_];
    __shared__ float srow[WPB_T][N_];

    int tid = threadIdx.x;
    for (int j = tid; j < N_; j += 256) {
        ssw[j] = g_sw[j]; ssb[j] = g_sb[j]; sss[j] = g_ss[j];
        sperm[j] = g_perm[j]; srank[j] = g_rank[j];
    }

    int wid  = tid >> 5;
    int lane = tid & 31;
    int t = blockIdx.x * WPB_T + wid;
    bool tv = (t < V_);

    if (tv) {
        const float4* rp = (const float4*)(w_out + (size_t)t * N_);
        float4* sp = (float4*)srow[wid];
        #pragma unroll
        for (int q = 0; q < 4; q++) sp[q * 32 + lane] = rp[q * 32 + lane];
    }
    __syncthreads();
    if (!tv) return;

    const float* row = srow[wid];

    // pass 1: per-lane suffix totals over its 16 positions
    float ta = 0.f, tb = 0.f, tc = 0.f;
    #pragma unroll
    for (int i = 15; i >= 0; i--) {
        int m = i * 32 + lane;
        float w = row[sperm[m]];
        ta = fmaf(w, ssw[m], ta);
        tb = fmaf(w, ssb[m], tb);
        tc = fmaf(w, sss[m], tc);
    }

    // inclusive suffix scan across lanes (lane l gets sum over lanes >= l)
    float ia = ta, ib = tb, ic = tc;
    #pragma unroll
    for (int off = 1; off < 32; off <<= 1) {
        float xa = __shfl_down_sync(0xffffffffu, ia, off);
        float xb = __shfl_down_sync(0xffffffffu, ib, off);
        float xc = __shfl_down_sync(0xffffffffu, ic, off);
        if (lane + off < 32) { ia += xa; ib += xb; ic += xc; }
    }
    float ba = ia - ta;      // exclusive suffix base (lanes strictly above)
    float bb = ib - tb;
    float bc = ic - tc;
    float totc = __shfl_sync(0xffffffffu, ic, 0);

    // pass 2: walk down, emit at used ranks
    float aa = ba, ab = bb, ac = bc;
    #pragma unroll
    for (int i = 15; i >= 0; i--) {
        int m = i * 32 + lane;
        float w = row[sperm[m]];
        aa = fmaf(w, ssw[m], aa);
        ab = fmaf(w, ssb[m], ab);
        ac = fmaf(w, sss[m], ac);
        int rk = srank[m];
        if (rk >= 0) {
            g_A[(size_t)rk * V4_ + t] = aa;
            g_D[(size_t)rk * V4_ + t] = ab - ac;
        }
    }

    if (lane == 0) {
        g_W0[t] = row[0];
        g_E[t]  = totc + b_out[t];
    }
}

// ----------------------------- K4: logits -----------------------------
__global__ void __launch_bounds__(256) k_logits(float* __restrict__ out) {
    __shared__ int   slist[CH2_];
    __shared__ int   srk[CH2_];
    __shared__ float sr[CH2_];
    __shared__ float sc[CH2_];

    {
        int p = threadIdx.x;
        int sid = g_list[blockIdx.y * CH2_ + p];
        slist[p] = sid;
        srk[p]   = g_krank[sid];
        sr[p]    = g_r[sid];
        sc[p]    = g_c[sid];
    }
    __syncthreads();

    int t0 = blockIdx.x * 1024 + threadIdx.x * 4;
    if (t0 >= V4_) return;

    const float4 w0 = *(const float4*)(g_W0 + t0);
    const float4 E  = *(const float4*)(g_E + t0);
    bool v0 = (t0     < V_);
    bool v1 = (t0 + 1 < V_);
    bool v2 = (t0 + 2 < V_);
    bool v3 = (t0 + 3 < V_);

    int kcur = -1;
    float4 A = make_float4(0.f, 0.f, 0.f, 0.f);
    float4 D = make_float4(0.f, 0.f, 0.f, 0.f);

    #pragma unroll 4
    for (int p = 0; p < CH2_; p++) {
        int rk = srk[p];
        if (rk != kcur) {
            A = *(const float4*)(g_A + (size_t)rk * V4_ + t0);
            float4 Dp = *(const float4*)(g_D + (size_t)rk * V4_ + t0);
            D = make_float4(Dp.x + E.x, Dp.y + E.y, Dp.z + E.z, Dp.w + E.w);
            kcur = rk;
        }
        float r = sr[p], c = sc[p];
        float x0 = fmaf(r, w0.x, fmaf(c, A.x, D.x));
        float x1 = fmaf(r, w0.y, fmaf(c, A.y, D.y));
        float x2 = fmaf(r, w0.z, fmaf(c, A.z, D.z));
        float x3 = fmaf(r, w0.w, fmaf(c, A.w, D.w));
        x0 = fminf(fmaxf(x0, -2.f), 2.f);
        x1 = fminf(fmaxf(x1, -2.f), 2.f);
        x2 = fminf(fmaxf(x2, -2.f), 2.f);
        x3 = fminf(fmaxf(x3, -2.f), 2.f);
        size_t o = (size_t)slist[p] * V_ + t0;
        if (v0) out[o]     = x0;
        if (v1) out[o + 1] = x1;
        if (v2) out[o + 2] = x2;
        if (v3) out[o + 3] = x3;
    }
}

// ----------------------------- launch -----------------------------
extern "C" void kernel_launch(void* const* d_in, const int* in_sizes, int n_in,
                              void* d_out, int out_size) {
    const int*   x      = (const int*)  d_in[0];
    const float* dt     = (const float*)d_in[1];
    const float* r0     = (const float*)d_in[2];
    const float* w_diff = (const float*)d_in[3];
    const float* b_diff = (const float*)d_in[4];
    const float* w_out  = (const float*)d_in[5];
    const float* b_out  = (const float*)d_in[6];
    float* out = (float*)d_out;
    size_t osz = (size_t)out_size;

    int write_score = (osz >= SCORE_OFF + (size_t)BS_ * S_) ? 1 : 0;

    k_init<<<1 + BS_ / 512, 512>>>(x, dt, r0, w_diff, b_diff, out, osz);
    k_step1<<<BS_, 256>>>(dt);
    k_step2<<<BS_, 512>>>(dt, out, write_score);

    k_tables_direct<<<(V_ + WPB_T - 1) / WPB_T, 256>>>(w_out, b_out);

    dim3 lg((V4_ + 1023) / 1024, NZ2_);
    k_logits<<<lg, 256>>>(out);
}

// round 8
// speedup vs baseline: 1.5122x; 1.4705x over previous
#include <cuda_runtime.h>
#include <math.h>
#include <float.h>

// Problem constants
#define B_    2
#define S_    2048
#define BS_   4096
#define V_    50257
#define V4_   50260          // V_ padded to multiple of 4 (row stride for tables)
#define N_    512
#define NM1_  511
#define NZ2_  16
#define CH2_  (BS_/NZ2_)     // 256 samples per z-slice
#define WPB_T 8              // warps (tokens) per block in k_tables_direct

#define SCORE_OFF  ((size_t)BS_ * (size_t)V_)
#define MEANDT_OFF (SCORE_OFF + (size_t)BS_ * (size_t)S_)

// ----------------------------- device scratch -----------------------------
__device__ float g_rv[BS_];
__device__ float g_k1[BS_];
__device__ float g_tgt[BS_];
__device__ float g_r[BS_];
__device__ float g_c[BS_];
__device__ int   g_list[BS_];
__device__ int   g_krank[BS_];
__device__ int   g_done;

__device__ float g_thresh[N_];   // sorted keys, normal order (for binary search)
// metadata in swizzled layout: slot(j) = (j%16)*32 + j/16  (j = sorted position)
__device__ float g_sw[N_];
__device__ float g_sb[N_];
__device__ float g_ss[N_];
__device__ int   g_perm[N_];     // original w_out column (perm(j)+1), 0 for dummy
__device__ int   g_rank[N_];     // compacted rank or -1, swizzled layout

__device__ __align__(16) float g_A [(size_t)N_ * V4_];   // suffix tables at used ranks
__device__ __align__(16) float g_D [(size_t)N_ * V4_];   // D' = suffB - suffC
__device__ __align__(16) float g_E [V4_];                // totalC + b_out
__device__ __align__(16) float g_W0[V4_];                // w_out[:,0]

// ----------------------------- helpers -----------------------------
__device__ __forceinline__ float blockReduceSum(float v, float* sh) {
    #pragma unroll
    for (int o = 16; o > 0; o >>= 1) v += __shfl_down_sync(0xffffffffu, v, o);
    int lane = threadIdx.x & 31;
    int w    = threadIdx.x >> 5;
    if (lane == 0) sh[w] = v;
    __syncthreads();
    if (w == 0) {
        v = (lane < (int)(blockDim.x >> 5)) ? sh[lane] : 0.f;
        #pragma unroll
        for (int o = 16; o > 0; o >>= 1) v += __shfl_down_sync(0xffffffffu, v, o);
        if (lane == 0) sh[0] = v;
    }
    __syncthreads();
    float r = sh[0];
    __syncthreads();
    return r;
}

__device__ __forceinline__ float clipf(float x, float lo, float hi) {
    return fminf(fmaxf(x, lo), hi);
}

// ----------------------------- K0: fused embed + sort (+ g_done reset) -----------------------------
__global__ void __launch_bounds__(512) k_init(const int* __restrict__ x,
                                              const float* __restrict__ dt,
                                              const float* __restrict__ r0,
                                              const float* __restrict__ w_diff,
                                              const float* __restrict__ b_diff,
                                              float* __restrict__ out, size_t out_size) {
    int tid = threadIdx.x;
    if (blockIdx.x != 0) {
        int gid = (blockIdx.x - 1) * 512 + tid;
        float r = r0[x[gid]];
        g_rv[gid] = r / fmaxf(fabsf(r), 1e-12f);
        if (gid == 0 && out_size > MEANDT_OFF) {
            float d0 = clipf(dt[0], 0.f, 1.f);
            float d1 = clipf(dt[1], 0.f, 1.f);
            out[MEANDT_OFF] = 0.5f * (d0 + d1);
        }
        return;
    }

    if (tid == 0) g_done = 0;    // reset for step2's last-block detection

    __shared__ float skey[N_];
    __shared__ int   sval[N_];

    float t = 3.0f;
    if (tid < NM1_) {
        float w = w_diff[tid], bb = b_diff[tid];
        t = 2.0f;
        if (w > 0.f && (w + bb) > 1.f)        t = (1.f - bb) / w;
        else if (w < 0.f && (w + bb) < -1.f)  t = (-1.f - bb) / w;
    }
    skey[tid] = t;
    sval[tid] = tid;
    __syncthreads();

    for (int ksz = 2; ksz <= N_; ksz <<= 1) {
        for (int jsz = ksz >> 1; jsz > 0; jsz >>= 1) {
            int ixj = tid ^ jsz;
            if (ixj > tid) {
                bool up = ((tid & ksz) == 0);
                float a = skey[tid], c = skey[ixj];
                bool sw = up ? (a > c) : (a < c);
                if (sw) {
                    skey[tid] = c; skey[ixj] = a;
                    int tmp = sval[tid]; sval[tid] = sval[ixj]; sval[ixj] = tmp;
                }
            }
            __syncthreads();
        }
    }

    int n = sval[tid];
    float key = skey[tid];
    g_thresh[tid] = key;
    int slot = ((tid & 15) << 5) | (tid >> 4);
    if (n < NM1_) {
        float w = w_diff[n], bb = b_diff[n];
        g_sw[slot]   = w;
        g_sb[slot]   = bb;
        g_ss[slot]   = (key >= 2.0f) ? 0.f : (w > 0.f ? 1.f : -1.f);
        g_perm[slot] = n + 1;
    } else {
        g_sw[slot] = 0.f; g_sb[slot] = 0.f; g_ss[slot] = 0.f;
        g_perm[slot] = 0;
    }
}

// ----------------------------- K1: score1 stats + k1 -----------------------------
__global__ void k_step1(const float* __restrict__ dt) {
    __shared__ float srow[S_];
    __shared__ float sred[32];
    int gid = blockIdx.x;
    int b = gid >> 11;
    int i = gid & (S_ - 1);

    for (int j = threadIdx.x; j < S_; j += blockDim.x) srow[j] = g_rv[b * S_ + j];
    __syncthreads();
    float ri = srow[i];

    float s1 = 0.f, s2 = 0.f;
    for (int j = threadIdx.x; j < S_; j += blockDim.x) {
        float d = fabsf(ri - srow[j]);
        s1 += d;
        s2 += d * d;
    }
    s1 = blockReduceSum(s1, sred);
    s2 = blockReduceSum(s2, sred);

    float mean = s1 * (1.f / (float)S_);
    float ssq  = fmaxf(s2 - s1 * mean, 0.f);
    float var  = ssq * (1.f / (float)(S_ - 1));
    float thr  = fmaxf(mean + 2.f * sqrtf(var), 1e-12f);
    float inv  = 1.f / thr;

    float acc = 0.f;
    for (int j = threadIdx.x; j < i; j += blockDim.x) {
        float d = fabsf(ri - srow[j]);
        if (d <= thr) acc += (1.f - d * inv) * srow[j];
    }
    acc = blockReduceSum(acc, sred);

    if (threadIdx.x == 0) {
        float dtc = clipf(dt[b], 0.f, 1.f);
        float k1  = clipf(dtc * acc, -1.f, 1.f);
        g_k1[gid]  = k1;
        g_tgt[gid] = ri + k1;
    }
}

// ----------------------------- K2: score2 + outputs + fused bucket (last block) ------------------
__global__ void __launch_bounds__(512) k_step2(const float* __restrict__ dt,
                                               float* __restrict__ out, int write_score) {
    __shared__ float srow[S_];
    __shared__ float sred[32];
    __shared__ int   sdone;
    int gid = blockIdx.x;
    int b = gid >> 11;
    int i = gid & (S_ - 1);
    int tid = threadIdx.x;

    for (int j = tid; j < S_; j += 512) srow[j] = g_tgt[b * S_ + j];
    __syncthreads();
    float ti = srow[i];

    float s1 = 0.f, s2 = 0.f;
    #pragma unroll
    for (int q = 0; q < 4; q++) {
        float d = fabsf(ti - srow[q * 512 + tid]);
        s1 += d;
        s2 += d * d;
    }
    s1 = blockReduceSum(s1, sred);
    s2 = blockReduceSum(s2, sred);

    float mean = s1 * (1.f / (float)S_);
    float ssq  = fmaxf(s2 - s1 * mean, 0.f);
    float var  = ssq * (1.f / (float)(S_ - 1));
    float thr  = fmaxf(mean + 2.f * sqrtf(var), 1e-12f);
    float inv  = 1.f / thr;

    float acc = 0.f, accs = 0.f;
    size_t rowoff = SCORE_OFF + (size_t)gid * S_;
    #pragma unroll
    for (int q = 0; q < 4; q++) {
        int j = q * 512 + tid;
        float d  = fabsf(ti - srow[j]);
        float sc = (j < i && d <= thr) ? (1.f - d * inv) : 0.f;
        if (write_score) __stcs(out + rowoff + j, sc);
        acc  += sc * srow[j];
        accs += sc;
    }
    acc  = blockReduceSum(acc, sred);
    accs = blockReduceSum(accs, sred);

    if (tid == 0) {
        float dtc = clipf(dt[b], 0.f, 1.f);
        float k2  = clipf(dtc * acc, -1.f, 1.f);
        float z   = g_rv[gid] + 0.5f * (g_k1[gid] + k2);
        g_r[gid]  = z / fmaxf(fabsf(z), 1e-12f);
        g_c[gid]  = clipf(accs * (1.f / (float)S_), 0.f, 1.f);
    }

    // ---- last-block-done: the final block to finish runs the bucket stage ----
    __threadfence();
    if (tid == 0) {
        int old = atomicAdd(&g_done, 1);
        sdone = (old == (int)gridDim.x - 1) ? 1 : 0;
    }
    __syncthreads();
    if (!sdone) return;

    // bucket: kidx + parallel scan + rank + scatter (512 threads)
    __shared__ float bthr[N_];
    __shared__ int   bs1[N_];
    __shared__ int   bs2[N_];
    __shared__ int   posA[N_];
    __shared__ int   rnkS[N_];

    bthr[tid] = g_thresh[tid];
    bs1[tid] = 0;
    __syncthreads();

    int kx[BS_ / 512];
    #pragma unroll
    for (int q = 0; q < BS_ / 512; q++) {
        int sid = q * 512 + tid;
        float c = g_c[sid];
        int lo = 0, hi = N_;
        while (lo < hi) {
            int mid = (lo + hi) >> 1;
            if (bthr[mid] <= c) lo = mid + 1; else hi = mid;
        }
        kx[q] = lo;                  // provably <= 511 (sentinel keys 2.0/3.0 > 1 >= c)
        atomicAdd(&bs1[lo], 1);
    }
    __syncthreads();

    int myc = bs1[tid];
    int myf = (myc > 0) ? 1 : 0;
    bs2[tid] = myf;
    __syncthreads();

    for (int off = 1; off < N_; off <<= 1) {
        int a = 0, bb2 = 0;
        if (tid >= off) { a = bs1[tid - off]; bb2 = bs2[tid - off]; }
        __syncthreads();
        bs1[tid] += a; bs2[tid] += bb2;
        __syncthreads();
    }

    posA[tid] = bs1[tid] - myc;
    int r = myf ? (bs2[tid] - 1) : -1;
    rnkS[tid] = r;
    g_rank[((tid & 15) << 5) | (tid >> 4)] = r;
    __syncthreads();

    #pragma unroll
    for (int q = 0; q < BS_ / 512; q++) {
        int sid = q * 512 + tid;
        int p = atomicAdd(&posA[kx[q]], 1);
        g_list[p] = sid;
        g_krank[sid] = rnkS[kx[q]];
    }
}

// ----------------------------- K3: tables directly from w_out rows -----------------------------
__global__ void __launch_bounds__(256) k_tables_direct(const float* __restrict__ w_out,
                                                       const float* __restrict__ b_out) {
    __shared__ float ssw[N_], ssb[N_], sss[N_];
    __shared__ int   sperm[N_], srank[N_];
    __shared__ float srow[WPB_T][N_];

    int tid = threadIdx.x;
    for (int j = tid; j < N_; j += 256) {
        ssw[j] = g_sw[j]; ssb[j] = g_sb[j]; sss[j] = g_ss[j];
        sperm[j] = g_perm[j]; srank[j] = g_rank[j];
    }

    int wid  = tid >> 5;
    int lane = tid & 31;
    int t = blockIdx.x * WPB_T + wid;
    bool tv = (t < V_);

    if (tv) {
        const float4* rp = (const float4*)(w_out + (size_t)t * N_);
        float4* sp = (float4*)srow[wid];
        #pragma unroll
        for (int q = 0; q < 4; q++) sp[q * 32 + lane] = rp[q * 32 + lane];
    }
    __syncthreads();
    if (!tv) return;

    const float* row = srow[wid];

    // pass 1: per-lane suffix totals over its 16 positions
    float ta = 0.f, tb = 0.f, tc = 0.f;
    #pragma unroll
    for (int i = 15; i >= 0; i--) {
        int m = i * 32 + lane;
        float w = row[sperm[m]];
        ta = fmaf(w, ssw[m], ta);
        tb = fmaf(w, ssb[m], tb);
        tc = fmaf(w, sss[m], tc);
    }

    // inclusive suffix scan across lanes
    float ia = ta, ib = tb, ic = tc;
    #pragma unroll
    for (int off = 1; off < 32; off <<= 1) {
        float xa = __shfl_down_sync(0xffffffffu, ia, off);
        float xb = __shfl_down_sync(0xffffffffu, ib, off);
        float xc = __shfl_down_sync(0xffffffffu, ic, off);
        if (lane + off < 32) { ia += xa; ib += xb; ic += xc; }
    }
    float ba = ia - ta;
    float bb = ib - tb;
    float bc = ic - tc;
    float totc = __shfl_sync(0xffffffffu, ic, 0);

    // pass 2: walk down, emit at used ranks
    float aa = ba, ab = bb, ac = bc;
    #pragma unroll
    for (int i = 15; i >= 0; i--) {
        int m = i * 32 + lane;
        float w = row[sperm[m]];
        aa = fmaf(w, ssw[m], aa);
        ab = fmaf(w, ssb[m], ab);
        ac = fmaf(w, sss[m], ac);
        int rk = srank[m];
        if (rk >= 0) {
            g_A[(size_t)rk * V4_ + t] = aa;
            g_D[(size_t)rk * V4_ + t] = ab - ac;
        }
    }

    if (lane == 0) {
        g_W0[t] = row[0];
        g_E[t]  = totc + b_out[t];
    }
}

// ----------------------------- K4: logits (strided tokens, streaming stores) --------------------
__global__ void __launch_bounds__(256) k_logits(float* __restrict__ out) {
    __shared__ int   slist[CH2_];
    __shared__ int   srk[CH2_];
    __shared__ float sr[CH2_];
    __shared__ float sc[CH2_];

    {
        int p = threadIdx.x;
        int sid = g_list[blockIdx.y * CH2_ + p];
        slist[p] = sid;
        srk[p]   = g_krank[sid];
        sr[p]    = g_r[sid];
        sc[p]    = g_c[sid];
    }
    __syncthreads();

    int tb = blockIdx.x * 1024 + threadIdx.x;   // strided tokens: tb + 256*q
    int   tq[4];
    int   tl[4];      // clamped load index (pad region of tables is initialized? use clamp to V4-1 is safe: g_* sized V4)
    bool  v[4];
    float w0[4], E[4];
    #pragma unroll
    for (int q = 0; q < 4; q++) {
        int t = tb + q * 256;
        tq[q] = t;
        v[q]  = (t < V_);
        int lt = (t < V4_) ? t : (V4_ - 1);
        tl[q] = lt;
        w0[q] = g_W0[lt];
        E[q]  = g_E[lt];
    }

    int kcur = -1;
    float A[4], D[4];
    #pragma unroll
    for (int q = 0; q < 4; q++) { A[q] = 0.f; D[q] = 0.f; }

    #pragma unroll 2
    for (int p = 0; p < CH2_; p++) {
        int rk = srk[p];
        if (rk != kcur) {
            size_t ro = (size_t)rk * V4_;
            #pragma unroll
            for (int q = 0; q < 4; q++) {
                A[q] = g_A[ro + tl[q]];
                D[q] = g_D[ro + tl[q]] + E[q];
            }
            kcur = rk;
        }
        float r = sr[p], c = sc[p];
        size_t base = (size_t)slist[p] * V_;
        #pragma unroll
        for (int q = 0; q < 4; q++) {
            float xq = fmaf(r, w0[q], fmaf(c, A[q], D[q]));
            xq = fminf(fmaxf(xq, -2.f), 2.f);
            if (v[q]) __stcs(out + base + tq[q], xq);
        }
    }
}

// ----------------------------- launch -----------------------------
extern "C" void kernel_launch(void* const* d_in, const int* in_sizes, int n_in,
                              void* d_out, int out_size) {
    const int*   x      = (const int*)  d_in[0];
    const float* dt     = (const float*)d_in[1];
    const float* r0     = (const float*)d_in[2];
    const float* w_diff = (const float*)d_in[3];
    const float* b_diff = (const float*)d_in[4];
    const float* w_out  = (const float*)d_in[5];
    const float* b_out  = (const float*)d_in[6];
    float* out = (float*)d_out;
    size_t osz = (size_t)out_size;

    int write_score = (osz >= SCORE_OFF + (size_t)BS_ * S_) ? 1 : 0;

    k_init<<<1 + BS_ / 512, 512>>>(x, dt, r0, w_diff, b_diff, out, osz);
    k_step1<<<BS_, 256>>>(dt);
    k_step2<<<BS_, 512>>>(dt, out, write_score);

    k_tables_direct<<<(V_ + WPB_T - 1) / WPB_T, 256>>>(w_out, b_out);

    dim3 lg((V4_ + 1023) / 1024, NZ2_);
    k_logits<<<lg, 256>>>(out);
}